// round 15
// baseline (speedup 1.0000x reference)
#include <cuda_runtime.h>
#include <cuda_bf16.h>
#include <math.h>
#include <stdint.h>

// Problem constants
#define SLEN 2048
#define DIN  2048
#define NH   32
#define NKV  8
#define HD   64
#define DOUT 2048   // NH*HD
#define KVD  512    // NKV*HD

// ---------------- scratch (device globals; no allocs allowed) ----------------
__device__ float g_qraw[SLEN * DOUT];   // [s][h*64+d]
__device__ float g_kraw[SLEN * KVD];    // [s][kv*64+d]
__device__ float g_vraw[SLEN * KVD];

// bf16 split operands (A activations row-major [M][K]; weights transposed [N][K])
__device__ __align__(256) __nv_bfloat16 g_xh[SLEN * DIN];
__device__ __align__(256) __nv_bfloat16 g_xl[SLEN * DIN];
__device__ __align__(256) __nv_bfloat16 g_wqh[DOUT * DIN];
__device__ __align__(256) __nv_bfloat16 g_wql[DOUT * DIN];
__device__ __align__(256) __nv_bfloat16 g_wkh[KVD * DIN];
__device__ __align__(256) __nv_bfloat16 g_wkl[KVD * DIN];
__device__ __align__(256) __nv_bfloat16 g_wvh[KVD * DIN];
__device__ __align__(256) __nv_bfloat16 g_wvl[KVD * DIN];
__device__ __align__(256) __nv_bfloat16 g_woh[DIN * DOUT];
__device__ __align__(256) __nv_bfloat16 g_wol[DIN * DOUT];
__device__ __align__(256) __nv_bfloat16 g_ch[SLEN * DOUT];
__device__ __align__(256) __nv_bfloat16 g_cl[SLEN * DOUT];

// attention operands, split bf16
__device__ __align__(256) __nv_bfloat16 g_qh[NH * SLEN * HD];   // [h][s][d]
__device__ __align__(256) __nv_bfloat16 g_ql[NH * SLEN * HD];
__device__ __align__(256) __nv_bfloat16 g_kbh[NKV * SLEN * HD]; // [kv][s][d]
__device__ __align__(256) __nv_bfloat16 g_kbl[NKV * SLEN * HD];
__device__ __align__(256) __nv_bfloat16 g_vth[NKV * HD * SLEN]; // [kv][d][s]
__device__ __align__(256) __nv_bfloat16 g_vtl[NKV * HD * SLEN];

// ---------------- PTX helpers ----------------
__device__ __forceinline__ uint32_t smem_u32(const void* p) {
    uint32_t a;
    asm("{ .reg .u64 t; cvta.to.shared.u64 t, %1; cvt.u32.u64 %0, t; }" : "=r"(a) : "l"(p));
    return a;
}

#define CP_ASYNC16(dst, src) \
    asm volatile("cp.async.cg.shared.global [%0], [%1], 16;" :: "r"(dst), "l"(src) : "memory")
#define CP_COMMIT() asm volatile("cp.async.commit_group;" ::: "memory")
#define CP_WAIT0()  asm volatile("cp.async.wait_group 0;" ::: "memory")
#define CP_WAIT1()  asm volatile("cp.async.wait_group 1;" ::: "memory")

__device__ __forceinline__ void ldsm_x4(uint32_t* r, uint32_t addr) {
    asm volatile("ldmatrix.sync.aligned.m8n8.x4.shared.b16 {%0,%1,%2,%3}, [%4];"
                 : "=r"(r[0]), "=r"(r[1]), "=r"(r[2]), "=r"(r[3]) : "r"(addr));
}
__device__ __forceinline__ void mma16816(float* c, const uint32_t* a, const uint32_t* b) {
    asm volatile("mma.sync.aligned.m16n8k16.row.col.f32.bf16.bf16.f32 "
                 "{%0,%1,%2,%3}, {%4,%5,%6,%7}, {%8,%9}, {%0,%1,%2,%3};"
                 : "+f"(c[0]), "+f"(c[1]), "+f"(c[2]), "+f"(c[3])
                 : "r"(a[0]), "r"(a[1]), "r"(a[2]), "r"(a[3]), "r"(b[0]), "r"(b[1]));
}

__device__ __forceinline__ uint32_t pack_bf16(float lo, float hi) {
    uint32_t r;
    asm("cvt.rn.bf16x2.f32 %0, %1, %2;" : "=r"(r) : "f"(hi), "f"(lo));
    return r;
}
__device__ __forceinline__ void split_pair(float a, float b, uint32_t& h, uint32_t& l) {
    h = pack_bf16(a, b);
    __nv_bfloat162 hb = *reinterpret_cast<__nv_bfloat162*>(&h);
    l = pack_bf16(a - __bfloat162float(hb.x), b - __bfloat162float(hb.y));
}

// ================= light GEMM: CTA 128x128, BK=64, 3-stage =================
#define GBK 64
#define GROW 144                         // smem row stride bytes (64 bf16 + 8 pad)
#define TILE_B (128 * GROW)              // 18432
#define STAGE_B (4 * TILE_B)             // 73728 (Ah, Al, Bh, Bl)
#define GEMM_SMEM (3 * STAGE_B)          // 221184

__device__ __forceinline__ void load_stage(uint32_t stage,
                                           const __nv_bfloat16* __restrict__ Ah,
                                           const __nv_bfloat16* __restrict__ Al,
                                           const __nv_bfloat16* __restrict__ Bh,
                                           const __nv_bfloat16* __restrict__ Bl,
                                           int K, int k0, int tid)
{
    const __nv_bfloat16* tp[4] = {Ah, Al, Bh, Bl};
#pragma unroll
    for (int t = 0; t < 4; t++) {
        const char* src_base = (const char*)tp[t] + (size_t)k0 * 2;
        uint32_t dtile = stage + t * TILE_B;
#pragma unroll
        for (int it = 0; it < 4; it++) {
            int u = tid + it * 256;
            int row = u >> 3;
            int ch = (u & 7) * 16;
            CP_ASYNC16(dtile + row * GROW + ch, src_base + (size_t)row * K * 2 + ch);
        }
    }
    CP_COMMIT();
}

__device__ __forceinline__ void hmma_gemm_body(const __nv_bfloat16* __restrict__ Ah,
                                               const __nv_bfloat16* __restrict__ Al,
                                               const __nv_bfloat16* __restrict__ Bh,
                                               const __nv_bfloat16* __restrict__ Bl,
                                               float* __restrict__ C, int K, int ldc,
                                               int gm0, int gn0)
{
    extern __shared__ char smem[];
    const uint32_t sb = smem_u32(smem);
    const int tid = threadIdx.x;
    const int wid = tid >> 5;
    const int lane = tid & 31;
    const int warpM = (wid >> 2) * 64;
    const int warpN = (wid & 3) * 32;
    const int NC = K / GBK;

    const __nv_bfloat16* Ah0 = Ah + (size_t)gm0 * K;
    const __nv_bfloat16* Al0 = Al + (size_t)gm0 * K;
    const __nv_bfloat16* Bh0 = Bh + (size_t)gn0 * K;
    const __nv_bfloat16* Bl0 = Bl + (size_t)gn0 * K;

    float acc[4][4][4];
#pragma unroll
    for (int i = 0; i < 4; i++)
#pragma unroll
        for (int j = 0; j < 4; j++)
#pragma unroll
            for (int v = 0; v < 4; v++) acc[i][j][v] = 0.f;

    const uint32_t a_off = (uint32_t)((warpM + (lane & 15)) * GROW + ((lane >> 4) << 4));
    const uint32_t b_rowsel = (uint32_t)((warpN + ((lane >> 4) & 1) * 8 + (lane & 7)) * GROW +
                                         (((lane >> 3) & 1) << 4));

    load_stage(sb + 0 * STAGE_B, Ah0, Al0, Bh0, Bl0, K, 0, tid);
    load_stage(sb + 1 * STAGE_B, Ah0, Al0, Bh0, Bl0, K, GBK, tid);

    for (int c = 0; c < NC; c++) {
        if (c + 1 < NC) { CP_WAIT1(); } else { CP_WAIT0(); }
        __syncthreads();

        if (c + 2 < NC)
            load_stage(sb + ((c + 2) % 3) * STAGE_B, Ah0, Al0, Bh0, Bl0, K, (c + 2) * GBK, tid);

        const uint32_t base = sb + (c % 3) * STAGE_B;
#pragma unroll
        for (int kk = 0; kk < 64; kk += 16) {
            uint32_t aH[4][4], aL[4][4], bH4[2][4], bL4[2][4];
#pragma unroll
            for (int mi = 0; mi < 4; mi++) {
                uint32_t ao = a_off + (uint32_t)(mi * 16 * GROW) + kk * 2;
                ldsm_x4(aH[mi], base + 0 * TILE_B + ao);
                ldsm_x4(aL[mi], base + 1 * TILE_B + ao);
            }
#pragma unroll
            for (int p = 0; p < 2; p++) {
                uint32_t bo = b_rowsel + (uint32_t)(p * 16 * GROW) + kk * 2;
                ldsm_x4(bH4[p], base + 2 * TILE_B + bo);
                ldsm_x4(bL4[p], base + 3 * TILE_B + bo);
            }
#pragma unroll
            for (int mi = 0; mi < 4; mi++)
#pragma unroll
                for (int p = 0; p < 2; p++) {
                    mma16816(acc[mi][2 * p],     aH[mi], bH4[p]);
                    mma16816(acc[mi][2 * p],     aL[mi], bH4[p]);
                    mma16816(acc[mi][2 * p],     aH[mi], bL4[p]);
                    mma16816(acc[mi][2 * p + 1], aH[mi], bH4[p] + 2);
                    mma16816(acc[mi][2 * p + 1], aL[mi], bH4[p] + 2);
                    mma16816(acc[mi][2 * p + 1], aH[mi], bL4[p] + 2);
                }
        }
    }

    const int r0 = lane >> 2;
    const int c0 = (lane & 3) * 2;
#pragma unroll
    for (int mi = 0; mi < 4; mi++)
#pragma unroll
        for (int nj = 0; nj < 4; nj++) {
            float* cp = C + (size_t)(gm0 + warpM + mi * 16 + r0) * ldc + gn0 + warpN + nj * 8 + c0;
            *reinterpret_cast<float2*>(cp) = make_float2(acc[mi][nj][0], acc[mi][nj][1]);
            *reinterpret_cast<float2*>(cp + 8 * ldc) = make_float2(acc[mi][nj][2], acc[mi][nj][3]);
        }
}

// ================= wide GEMM: CTA 128x256, BK=64, 2-stage, warp tile 64x64 =================
#define WA_TILE (128 * GROW)             // 18432 per (h|l)
#define WB_TILE (256 * GROW)             // 36864 per (h|l)
#define WSTG (2 * WA_TILE + 2 * WB_TILE) // 110592

__device__ __forceinline__ void load_stage_wide(uint32_t stage,
                                                const __nv_bfloat16* __restrict__ Ah,
                                                const __nv_bfloat16* __restrict__ Al,
                                                const __nv_bfloat16* __restrict__ Bh,
                                                const __nv_bfloat16* __restrict__ Bl,
                                                int K, int k0, int tid)
{
    {
        const __nv_bfloat16* tp[2] = {Ah, Al};
#pragma unroll
        for (int t = 0; t < 2; t++) {
            const char* src = (const char*)tp[t] + (size_t)k0 * 2;
            uint32_t dtile = stage + t * WA_TILE;
#pragma unroll
            for (int it = 0; it < 4; it++) {
                int u = tid + it * 256;       // 0..1023 -> 128 rows
                int row = u >> 3;
                int ch = (u & 7) * 16;
                CP_ASYNC16(dtile + row * GROW + ch, src + (size_t)row * K * 2 + ch);
            }
        }
    }
    {
        const __nv_bfloat16* tp[2] = {Bh, Bl};
#pragma unroll
        for (int t = 0; t < 2; t++) {
            const char* src = (const char*)tp[t] + (size_t)k0 * 2;
            uint32_t dtile = stage + 2 * WA_TILE + t * WB_TILE;
#pragma unroll
            for (int it = 0; it < 8; it++) {
                int u = tid + it * 256;       // 0..2047 -> 256 rows
                int row = u >> 3;
                int ch = (u & 7) * 16;
                CP_ASYNC16(dtile + row * GROW + ch, src + (size_t)row * K * 2 + ch);
            }
        }
    }
    CP_COMMIT();
}

__device__ __forceinline__ void hmma_gemm_wide(const __nv_bfloat16* __restrict__ Ah,
                                               const __nv_bfloat16* __restrict__ Al,
                                               const __nv_bfloat16* __restrict__ Bh,
                                               const __nv_bfloat16* __restrict__ Bl,
                                               float* __restrict__ C, int K, int ldc,
                                               int gm0, int gn0)
{
    extern __shared__ char smem[];
    const uint32_t sb = smem_u32(smem);
    const int tid = threadIdx.x;
    const int wid = tid >> 5;
    const int lane = tid & 31;
    const int warpM = (wid >> 2) * 64;       // 2 M-groups
    const int warpN = (wid & 3) * 64;        // 4 N-groups of 64
    const int NC = K / GBK;

    const __nv_bfloat16* Ah0 = Ah + (size_t)gm0 * K;
    const __nv_bfloat16* Al0 = Al + (size_t)gm0 * K;
    const __nv_bfloat16* Bh0 = Bh + (size_t)gn0 * K;
    const __nv_bfloat16* Bl0 = Bl + (size_t)gn0 * K;

    float acc[4][8][4];
#pragma unroll
    for (int i = 0; i < 4; i++)
#pragma unroll
        for (int j = 0; j < 8; j++)
#pragma unroll
            for (int v = 0; v < 4; v++) acc[i][j][v] = 0.f;

    const uint32_t a_off = (uint32_t)((warpM + (lane & 15)) * GROW + ((lane >> 4) << 4));
    const uint32_t b_rowsel = (uint32_t)((warpN + ((lane >> 4) & 1) * 8 + (lane & 7)) * GROW +
                                         (((lane >> 3) & 1) << 4));

    load_stage_wide(sb + 0 * WSTG, Ah0, Al0, Bh0, Bl0, K, 0, tid);
    load_stage_wide(sb + 1 * WSTG, Ah0, Al0, Bh0, Bl0, K, GBK, tid);

    for (int c = 0; c < NC; c++) {
        if (c + 1 < NC) { CP_WAIT1(); } else { CP_WAIT0(); }
        __syncthreads();

        const uint32_t base = sb + (c & 1) * WSTG;
#pragma unroll 1
        for (int kk = 0; kk < 4; kk++) {
            uint32_t aH[4][4], aL[4][4];
#pragma unroll
            for (int mi = 0; mi < 4; mi++) {
                uint32_t ao = a_off + (uint32_t)(mi * 16 * GROW) + kk * 32;
                ldsm_x4(aH[mi], base + ao);
                ldsm_x4(aL[mi], base + WA_TILE + ao);
            }
#pragma unroll
            for (int p = 0; p < 4; p++) {
                uint32_t bo = b_rowsel + (uint32_t)(p * 16 * GROW) + kk * 32;
                uint32_t bH4[4], bL4[4];
                ldsm_x4(bH4, base + 2 * WA_TILE + bo);
                ldsm_x4(bL4, base + 2 * WA_TILE + WB_TILE + bo);
#pragma unroll
                for (int mi = 0; mi < 4; mi++) {
                    mma16816(acc[mi][2 * p],     aH[mi], bH4);
                    mma16816(acc[mi][2 * p],     aL[mi], bH4);
                    mma16816(acc[mi][2 * p],     aH[mi], bL4);
                    mma16816(acc[mi][2 * p + 1], aH[mi], bH4 + 2);
                    mma16816(acc[mi][2 * p + 1], aL[mi], bH4 + 2);
                    mma16816(acc[mi][2 * p + 1], aH[mi], bL4 + 2);
                }
            }
        }
        __syncthreads();
        if (c + 2 < NC)
            load_stage_wide(base, Ah0, Al0, Bh0, Bl0, K, (c + 2) * GBK, tid);
    }

    const int r0 = lane >> 2;
    const int c0 = (lane & 3) * 2;
#pragma unroll
    for (int mi = 0; mi < 4; mi++)
#pragma unroll
        for (int nj = 0; nj < 8; nj++) {
            float* cp = C + (size_t)(gm0 + warpM + mi * 16 + r0) * ldc + gn0 + warpN + nj * 8 + c0;
            *reinterpret_cast<float2*>(cp) = make_float2(acc[mi][nj][0], acc[mi][nj][1]);
            *reinterpret_cast<float2*>(cp + 8 * ldc) = make_float2(acc[mi][nj][2], acc[mi][nj][3]);
        }
}

// Fused Q/K/V projections: 128 wide q CTAs (heavy, scheduled first) + 64 k + 64 v light.
__global__ __launch_bounds__(256, 1) void gemm_qkv_kernel() {
    const int bid = blockIdx.x;
    if (bid < 128) {
        hmma_gemm_wide(g_xh, g_xl, g_wqh, g_wql, g_qraw, DIN, DOUT,
                       (bid >> 3) * 128, (bid & 7) * 256);
    } else if (bid < 192) {
        const int b = bid - 128;
        hmma_gemm_body(g_xh, g_xl, g_wkh, g_wkl, g_kraw, DIN, KVD,
                       (b >> 2) * 128, (b & 3) * 128);
    } else {
        const int b = bid - 192;
        hmma_gemm_body(g_xh, g_xl, g_wvh, g_wvl, g_vraw, DIN, KVD,
                       (b >> 2) * 128, (b & 3) * 128);
    }
}

__global__ __launch_bounds__(256, 1) void gemm_o_kernel(float* __restrict__ out) {
    hmma_gemm_wide(g_ch, g_cl, g_woh, g_wol, out, DOUT, DIN,
                   blockIdx.y * 128, blockIdx.x * 256);
}

// ---------------- converts ----------------
__device__ __forceinline__ void wconv_body(const float* __restrict__ W,
                                           __nv_bfloat16* __restrict__ Bh,
                                           __nv_bfloat16* __restrict__ Bl,
                                           int R, int Cc, int bx, int by)
{
    __shared__ float t[32][33];
    const int c0 = bx * 32;
    const int r0 = by * 32;
    const int tx = threadIdx.x;
    const int ty = threadIdx.y;
#pragma unroll
    for (int i = ty; i < 32; i += 8)
        t[i][tx] = W[(size_t)(r0 + i) * Cc + c0 + tx];
    __syncthreads();
#pragma unroll
    for (int i = ty; i < 32; i += 8) {
        float v = t[tx][i];
        size_t o = (size_t)(c0 + i) * R + r0 + tx;
        __nv_bfloat16 h = __float2bfloat16(v);
        Bh[o] = h;
        Bl[o] = __float2bfloat16(v - __bfloat162float(h));
    }
}

// fused converts: x split (8192) + wq (4096) + wk (1024) + wv (1024) + wo (4096) = 18432 CTAs
__global__ void conv_all_kernel(const float* __restrict__ x,
                                const float* __restrict__ Wq, const float* __restrict__ Wk,
                                const float* __restrict__ Wv, const float* __restrict__ Wo)
{
    int b = blockIdx.x;
    if (b < 8192) {
        int tid = threadIdx.y * 32 + threadIdx.x;
        int i = (b * 256 + tid) * 2;
        float2 v = *reinterpret_cast<const float2*>(x + i);
        uint32_t h, l;
        split_pair(v.x, v.y, h, l);
        reinterpret_cast<uint32_t*>(g_xh)[i >> 1] = h;
        reinterpret_cast<uint32_t*>(g_xl)[i >> 1] = l;
        return;
    }
    b -= 8192;
    if (b < 4096) {
        wconv_body(Wq, g_wqh, g_wql, DIN, DOUT, b & 63, b >> 6);
    } else if (b < 5120) {
        b -= 4096;
        wconv_body(Wk, g_wkh, g_wkl, DIN, KVD, b & 15, b >> 4);
    } else if (b < 6144) {
        b -= 5120;
        wconv_body(Wv, g_wvh, g_wvl, DIN, KVD, b & 15, b >> 4);
    } else {
        b -= 6144;
        wconv_body(Wo, g_woh, g_wol, DOUT, DIN, b & 63, b >> 6);
    }
}

// V: fp32 [s][kv*64+d] -> split bf16 transposed [kv][d][s]
__global__ void vsplit_kernel() {
    __shared__ float t[32][33];
    const int s0 = blockIdx.x * 32;
    const int d0 = blockIdx.y * 32;
    const int kv = blockIdx.z;
    const int tx = threadIdx.x;
    const int ty = threadIdx.y;
#pragma unroll
    for (int i = ty; i < 32; i += 8)
        t[i][tx] = g_vraw[(size_t)(s0 + i) * KVD + kv * 64 + d0 + tx];
    __syncthreads();
#pragma unroll
    for (int i = ty; i < 32; i += 8) {
        float v = t[tx][i];
        size_t o = ((size_t)kv * 64 + d0 + i) * SLEN + s0 + tx;
        __nv_bfloat16 h = __float2bfloat16(v);
        g_vth[o] = h;
        g_vtl[o] = __float2bfloat16(v - __bfloat162float(h));
    }
}

// ---------------- RMSNorm + RoPE -> split bf16 (vectorized float2) ----------------
// block (32, 8): warp ty handles unit u = by*8+ty; thread handles d = 2*tx, 2*tx+1.
__global__ void normrope_kernel(const float* __restrict__ cosb,
                                const float* __restrict__ sinb,
                                const float* __restrict__ qw,
                                const float* __restrict__ kw)
{
    const int s = blockIdx.x;
    const int ty = threadIdx.y;
    const int tx = threadIdx.x;
    const int u = blockIdx.y * 8 + ty;   // 0..39
    const int d2 = tx * 2;
    __shared__ float sh[8][64];

    float2 val;
    float2 w;
    if (u < 32) {
        val = *reinterpret_cast<const float2*>(&g_qraw[(size_t)s * DOUT + u * 64 + d2]);
        w = *reinterpret_cast<const float2*>(&qw[d2]);
    } else {
        val = *reinterpret_cast<const float2*>(&g_kraw[(size_t)s * KVD + (u - 32) * 64 + d2]);
        w = *reinterpret_cast<const float2*>(&kw[d2]);
    }
    float sq = val.x * val.x + val.y * val.y;
#pragma unroll
    for (int mk = 16; mk; mk >>= 1) sq += __shfl_xor_sync(0xffffffffu, sq, mk);
    const float rn = rsqrtf(sq * (1.0f / 64.0f) + 1e-6f);
    float2 xn = make_float2(val.x * rn * w.x, val.y * rn * w.y);
    sh[ty][d2] = xn.x;
    sh[ty][d2 + 1] = xn.y;
    __syncthreads();
    float2 rot;
    if (tx < 16) { rot = make_float2(-sh[ty][d2 + 32], -sh[ty][d2 + 33]); }
    else         { rot = make_float2( sh[ty][d2 - 32],  sh[ty][d2 - 31]); }
    float2 cs = *reinterpret_cast<const float2*>(&cosb[s * 64 + d2]);
    float2 sn = *reinterpret_cast<const float2*>(&sinb[s * 64 + d2]);
    float o0 = xn.x * cs.x + rot.x * sn.x;
    float o1 = xn.y * cs.y + rot.y * sn.y;
    uint32_t hh, ll;
    split_pair(o0, o1, hh, ll);
    if (u < 32) {
        size_t idx = ((size_t)u * SLEN + s) * 64 + d2;
        *reinterpret_cast<uint32_t*>(&g_qh[idx]) = hh;
        *reinterpret_cast<uint32_t*>(&g_ql[idx]) = ll;
    } else {
        size_t idx = ((size_t)(u - 32) * SLEN + s) * 64 + d2;
        *reinterpret_cast<uint32_t*>(&g_kbh[idx]) = hh;
        *reinterpret_cast<uint32_t*>(&g_kbl[idx]) = ll;
    }
}

// ---------------- Flash attention (HMMA split-bf16, causal, GQA) ----------------
// grid (32 heads, 16 q-blocks), 256 threads (8 warps x 16 rows). Q tile 128, KV tile 128.
#define ATS 144                       // K/Q tile row stride (128B rows + pad)
#define ATSV 272                      // V tile row stride (256B rows + pad)
#define QTILE (128 * ATS)             // 18432
#define KT2 (128 * ATS)               // 18432 (K hi or lo, 128 kv rows)
#define VT2 (64 * ATSV)               // 17408 (V hi or lo, 64 d rows x 256B)
#define STG_ATT (2 * KT2 + 2 * VT2)   // 71680
#define ATT_SMEM (2 * QTILE + 2 * STG_ATT)   // 180224

__global__ __launch_bounds__(256) void attn_kernel()
{
    extern __shared__ char smem[];
    const uint32_t sb = smem_u32(smem);
    const int tid = threadIdx.x;
    const int lane = tid & 31;
    const int wid = tid >> 5;
    const int h = blockIdx.x;
    const int qb = 15 - (int)blockIdx.y;    // heavy blocks first
    const int s0 = qb * 128;
    const int kvh = h >> 2;

    const uint32_t SQH = sb, SQL = sb + QTILE, SKV = sb + 2 * QTILE;

    const char* qh = (const char*)g_qh + (((size_t)h * SLEN + s0) * 64) * 2;
    const char* ql = (const char*)g_ql + (((size_t)h * SLEN + s0) * 64) * 2;
    const char* kh = (const char*)g_kbh + ((size_t)kvh * SLEN * 64) * 2;
    const char* kl = (const char*)g_kbl + ((size_t)kvh * SLEN * 64) * 2;
    const char* vh = (const char*)g_vth + ((size_t)kvh * 64 * SLEN) * 2;
    const char* vl = (const char*)g_vtl + ((size_t)kvh * 64 * SLEN) * 2;

    // Q tiles (hi, lo): 128 rows x 128B
#pragma unroll
    for (int i = 0; i < 4; i++) {
        int u = tid + i * 256;
        int row = u >> 3;
        int ch = (u & 7) * 16;
        CP_ASYNC16(SQH + row * ATS + ch, qh + (size_t)row * 128 + ch);
        CP_ASYNC16(SQL + row * ATS + ch, ql + (size_t)row * 128 + ch);
    }
    // K/V stage 0: K = 128 kv rows x 128B; V = 64 d rows x 256B
    {
        uint32_t base = SKV;
#pragma unroll
        for (int i = 0; i < 4; i++) {
            int u = tid + i * 256;          // 0..1023
            int krow = u >> 3;
            int kch = (u & 7) * 16;
            CP_ASYNC16(base + 0 * KT2 + krow * ATS + kch, kh + (size_t)krow * 128 + kch);
            CP_ASYNC16(base + 1 * KT2 + krow * ATS + kch, kl + (size_t)krow * 128 + kch);
            int vrow = u >> 4;              // 0..63
            int vch = (u & 15) * 16;        // 0..240
            CP_ASYNC16(base + 2 * KT2 + 0 * VT2 + vrow * ATSV + vch, vh + (size_t)vrow * SLEN * 2 + vch);
            CP_ASYNC16(base + 2 * KT2 + 1 * VT2 + vrow * ATSV + vch, vl + (size_t)vrow * SLEN * 2 + vch);
        }
    }
    CP_COMMIT();

    const int warpM = wid * 16;
    const uint32_t a_off = (uint32_t)((warpM + (lane & 15)) * ATS + ((lane >> 4) << 4));
    const uint32_t b_rowselK = (uint32_t)((((lane >> 4) & 1) * 8 + (lane & 7)) * ATS +
                                          (((lane >> 3) & 1) << 4));
    const uint32_t b_rowselV = (uint32_t)((((lane >> 4) & 1) * 8 + (lane & 7)) * ATSV +
                                          (((lane >> 3) & 1) << 4));

    float m0 = -1e30f, m1 = -1e30f, l0 = 0.f, l1 = 0.f;
    float o[8][4];
#pragma unroll
    for (int j = 0; j < 8; j++)
#pragma unroll
        for (int v = 0; v < 4; v++) o[j][v] = 0.f;

    const float scale = 0.125f;

    for (int kb = 0; kb <= qb; kb++) {
        const int st = kb & 1;
        const int t0 = kb * 128;
        if (kb < qb) {
            uint32_t base = SKV + (st ^ 1) * STG_ATT;
            const size_t t1 = (size_t)(kb + 1) * 128;
#pragma unroll
            for (int i = 0; i < 4; i++) {
                int u = tid + i * 256;
                int krow = u >> 3;
                int kch = (u & 7) * 16;
                CP_ASYNC16(base + 0 * KT2 + krow * ATS + kch, kh + (t1 + krow) * 128 + kch);
                CP_ASYNC16(base + 1 * KT2 + krow * ATS + kch, kl + (t1 + krow) * 128 + kch);
                int vrow = u >> 4;
                int vch = (u & 15) * 16;
                CP_ASYNC16(base + 2 * KT2 + 0 * VT2 + vrow * ATSV + vch,
                           vh + (size_t)vrow * SLEN * 2 + t1 * 2 + vch);
                CP_ASYNC16(base + 2 * KT2 + 1 * VT2 + vrow * ATSV + vch,
                           vl + (size_t)vrow * SLEN * 2 + t1 * 2 + vch);
            }
            CP_COMMIT();
            CP_WAIT1();
        } else {
            CP_WAIT0();
        }
        __syncthreads();

        const uint32_t KH = SKV + st * STG_ATT;
        const uint32_t KL = KH + KT2;
        const uint32_t VH = KH + 2 * KT2;
        const uint32_t VL = VH + VT2;

        // ---- scores S = Q K^T (16 rows x 128 cols per warp) ----
        float s_acc[16][4];
#pragma unroll
        for (int j = 0; j < 16; j++)
#pragma unroll
            for (int v = 0; v < 4; v++) s_acc[j][v] = 0.f;

#pragma unroll
        for (int kk = 0; kk < 4; kk++) {
            uint32_t aH[4], aL[4];
            ldsm_x4(aH, SQH + a_off + kk * 32);
            ldsm_x4(aL, SQL + a_off + kk * 32);
#pragma unroll
            for (int p = 0; p < 8; p++) {
                uint32_t bo = (uint32_t)(p * 16 * ATS) + b_rowselK + kk * 32;
                uint32_t bH4[4], bL4[4];
                ldsm_x4(bH4, KH + bo);
                ldsm_x4(bL4, KL + bo);
                mma16816(s_acc[2 * p],     aH, bH4);
                mma16816(s_acc[2 * p],     aL, bH4);
                mma16816(s_acc[2 * p],     aH, bL4);
                mma16816(s_acc[2 * p + 1], aH, bH4 + 2);
                mma16816(s_acc[2 * p + 1], aL, bH4 + 2);
                mma16816(s_acc[2 * p + 1], aH, bL4 + 2);
            }
        }

#pragma unroll
        for (int j = 0; j < 16; j++)
#pragma unroll
            for (int v = 0; v < 4; v++) s_acc[j][v] *= scale;

        // causal mask (only the diagonal iteration can clip)
        if (t0 + 127 > s0 + warpM) {
            const int rg0 = s0 + warpM + (lane >> 2);
#pragma unroll
            for (int nj = 0; nj < 16; nj++) {
                const int cg = t0 + nj * 8 + (lane & 3) * 2;
#pragma unroll
                for (int e = 0; e < 2; e++) {
                    if (cg + e > rg0) s_acc[nj][e] = -1e30f;
                    if (cg + e > rg0 + 8) s_acc[nj][2 + e] = -1e30f;
                }
            }
        }

        // ---- online softmax ----
        float mx0 = -1e30f, mx1 = -1e30f;
#pragma unroll
        for (int nj = 0; nj < 16; nj++) {
            mx0 = fmaxf(mx0, fmaxf(s_acc[nj][0], s_acc[nj][1]));
            mx1 = fmaxf(mx1, fmaxf(s_acc[nj][2], s_acc[nj][3]));
        }
        mx0 = fmaxf(mx0, __shfl_xor_sync(0xffffffffu, mx0, 1));
        mx0 = fmaxf(mx0, __shfl_xor_sync(0xffffffffu, mx0, 2));
        mx1 = fmaxf(mx1, __shfl_xor_sync(0xffffffffu, mx1, 1));
        mx1 = fmaxf(mx1, __shfl_xor_sync(0xffffffffu, mx1, 2));
        const float M0 = fmaxf(m0, mx0), M1 = fmaxf(m1, mx1);
        const float corr0 = __expf(m0 - M0), corr1 = __expf(m1 - M1);
        m0 = M0; m1 = M1;

        float rs0 = 0.f, rs1 = 0.f;
#pragma unroll
        for (int nj = 0; nj < 16; nj++) {
            s_acc[nj][0] = __expf(s_acc[nj][0] - M0);
            s_acc[nj][1] = __expf(s_acc[nj][1] - M0);
            s_acc[nj][2] = __expf(s_acc[nj][2] - M1);
            s_acc[nj][3] = __expf(s_acc[nj][3] - M1);
            rs0 += s_acc[nj][0] + s_acc[nj][1];
            rs1 += s_acc[nj][2] + s_acc[nj][3];
        }
        rs0 += __shfl_xor_sync(0xffffffffu, rs0, 1);
        rs0 += __shfl_xor_sync(0xffffffffu, rs0, 2);
        rs1 += __shfl_xor_sync(0xffffffffu, rs1, 1);
        rs1 += __shfl_xor_sync(0xffffffffu, rs1, 2);
        l0 = l0 * corr0 + rs0;
        l1 = l1 * corr1 + rs1;

#pragma unroll
        for (int j = 0; j < 8; j++) {
            o[j][0] *= corr0; o[j][1] *= corr0;
            o[j][2] *= corr1; o[j][3] *= corr1;
        }

        // ---- PV: o += P V^T ----
#pragma unroll
        for (int kt = 0; kt < 8; kt++) {
            uint32_t pH[4], pL[4];
            split_pair(s_acc[2 * kt][0],     s_acc[2 * kt][1],     pH[0], pL[0]);
            split_pair(s_acc[2 * kt][2],     s_acc[2 * kt][3],     pH[1], pL[1]);
            split_pair(s_acc[2 * kt + 1][0], s_acc[2 * kt + 1][1], pH[2], pL[2]);
            split_pair(s_acc[2 * kt + 1][2], s_acc[2 * kt + 1][3], pH[3], pL[3]);
#pragma unroll
            for (int p = 0; p < 4; p++) {
                uint32_t vo = (uint32_t)(p * 16 * ATSV) + b_rowselV + kt * 32;
                uint32_t vH4[4], vL4[4];
                ldsm_x4(vH4, VH + vo);
                ldsm_x4(vL4, VL + vo);
                mma16816(o[2 * p],     pH, vH4);
                mma16816(o[2 * p],     pL, vH4);
                mma16816(o[2 * p],     pH, vL4);
                mma16816(o[2 * p + 1], pH, vH4 + 2);
                mma16816(o[2 * p + 1], pL, vH4 + 2);
                mma16816(o[2 * p + 1], pH, vL4 + 2);
            }
        }
        __syncthreads();
    }

    const float inv0 = 1.0f / l0, inv1 = 1.0f / l1;
    const int r0 = s0 + warpM + (lane >> 2);
    const int r1 = r0 + 8;
    const int cb = h * 64 + (lane & 3) * 2;
#pragma unroll
    for (int dj = 0; dj < 8; dj++) {
        const int col = cb + dj * 8;
        uint32_t hh, ll;
        split_pair(o[dj][0] * inv0, o[dj][1] * inv0, hh, ll);
        *reinterpret_cast<uint32_t*>(&g_ch[(size_t)r0 * DOUT + col]) = hh;
        *reinterpret_cast<uint32_t*>(&g_cl[(size_t)r0 * DOUT + col]) = ll;
        split_pair(o[dj][2] * inv1, o[dj][3] * inv1, hh, ll);
        *reinterpret_cast<uint32_t*>(&g_ch[(size_t)r1 * DOUT + col]) = hh;
        *reinterpret_cast<uint32_t*>(&g_cl[(size_t)r1 * DOUT + col]) = ll;
    }
}

// ---------------- launch ----------------
extern "C" void kernel_launch(void* const* d_in, const int* in_sizes, int n_in,
                              void* d_out, int out_size)
{
    const float* x    = (const float*)d_in[0];
    const float* cosb = (const float*)d_in[2];
    const float* sinb = (const float*)d_in[3];
    const float* Wq   = (const float*)d_in[4];
    const float* Wk   = (const float*)d_in[5];
    const float* Wv   = (const float*)d_in[6];
    const float* Wo   = (const float*)d_in[7];
    const float* qw   = (const float*)d_in[8];
    const float* kw   = (const float*)d_in[9];
    float* out = (float*)d_out;

    (void)in_sizes; (void)n_in; (void)out_size;

    cudaFuncSetAttribute(gemm_qkv_kernel, cudaFuncAttributeMaxDynamicSharedMemorySize, GEMM_SMEM);
    cudaFuncSetAttribute(gemm_o_kernel,   cudaFuncAttributeMaxDynamicSharedMemorySize, GEMM_SMEM);
    cudaFuncSetAttribute(attn_kernel,     cudaFuncAttributeMaxDynamicSharedMemorySize, ATT_SMEM);

    conv_all_kernel<<<18432, dim3(32, 8)>>>(x, Wq, Wk, Wv, Wo);

    gemm_qkv_kernel<<<256, 256, GEMM_SMEM>>>();

    normrope_kernel<<<dim3(SLEN, 5), dim3(32, 8)>>>(cosb, sinb, qw, kw);
    vsplit_kernel<<<dim3(SLEN / 32, 2, NKV), dim3(32, 8)>>>();

    attn_kernel<<<dim3(NH, 16), 256, ATT_SMEM>>>();

    gemm_o_kernel<<<dim3(DOUT / 256, SLEN / 128), 256, GEMM_SMEM>>>(out);
}

// round 16
// speedup vs baseline: 1.0209x; 1.0209x over previous
#include <cuda_runtime.h>
#include <cuda_bf16.h>
#include <math.h>
#include <stdint.h>

// Problem constants
#define SLEN 2048
#define DIN  2048
#define NH   32
#define NKV  8
#define HD   64
#define DOUT 2048   // NH*HD
#define KVD  512    // NKV*HD

// ---------------- scratch (device globals; no allocs allowed) ----------------
__device__ float g_qraw[SLEN * DOUT];   // [s][h*64+d]
__device__ float g_kraw[SLEN * KVD];    // [s][kv*64+d]
__device__ float g_vraw[SLEN * KVD];

// bf16 split operands (A activations row-major [M][K]; weights transposed [N][K])
__device__ __align__(256) __nv_bfloat16 g_xh[SLEN * DIN];
__device__ __align__(256) __nv_bfloat16 g_xl[SLEN * DIN];
__device__ __align__(256) __nv_bfloat16 g_wqh[DOUT * DIN];
__device__ __align__(256) __nv_bfloat16 g_wql[DOUT * DIN];
__device__ __align__(256) __nv_bfloat16 g_wkh[KVD * DIN];
__device__ __align__(256) __nv_bfloat16 g_wkl[KVD * DIN];
__device__ __align__(256) __nv_bfloat16 g_wvh[KVD * DIN];
__device__ __align__(256) __nv_bfloat16 g_wvl[KVD * DIN];
__device__ __align__(256) __nv_bfloat16 g_woh[DIN * DOUT];
__device__ __align__(256) __nv_bfloat16 g_wol[DIN * DOUT];
__device__ __align__(256) __nv_bfloat16 g_ch[SLEN * DOUT];
__device__ __align__(256) __nv_bfloat16 g_cl[SLEN * DOUT];

// attention operands, split bf16
__device__ __align__(256) __nv_bfloat16 g_qh[NH * SLEN * HD];   // [h][s][d]
__device__ __align__(256) __nv_bfloat16 g_ql[NH * SLEN * HD];
__device__ __align__(256) __nv_bfloat16 g_kbh[NKV * SLEN * HD]; // [kv][s][d]
__device__ __align__(256) __nv_bfloat16 g_kbl[NKV * SLEN * HD];
__device__ __align__(256) __nv_bfloat16 g_vth[NKV * HD * SLEN]; // [kv][d][s]
__device__ __align__(256) __nv_bfloat16 g_vtl[NKV * HD * SLEN];

// ---------------- PTX helpers ----------------
__device__ __forceinline__ uint32_t smem_u32(const void* p) {
    uint32_t a;
    asm("{ .reg .u64 t; cvta.to.shared.u64 t, %1; cvt.u32.u64 %0, t; }" : "=r"(a) : "l"(p));
    return a;
}

#define CP_ASYNC16(dst, src) \
    asm volatile("cp.async.cg.shared.global [%0], [%1], 16;" :: "r"(dst), "l"(src) : "memory")
#define CP_COMMIT() asm volatile("cp.async.commit_group;" ::: "memory")
#define CP_WAIT0()  asm volatile("cp.async.wait_group 0;" ::: "memory")
#define CP_WAIT1()  asm volatile("cp.async.wait_group 1;" ::: "memory")

__device__ __forceinline__ void ldsm_x4(uint32_t* r, uint32_t addr) {
    asm volatile("ldmatrix.sync.aligned.m8n8.x4.shared.b16 {%0,%1,%2,%3}, [%4];"
                 : "=r"(r[0]), "=r"(r[1]), "=r"(r[2]), "=r"(r[3]) : "r"(addr));
}
__device__ __forceinline__ void mma16816(float* c, const uint32_t* a, const uint32_t* b) {
    asm volatile("mma.sync.aligned.m16n8k16.row.col.f32.bf16.bf16.f32 "
                 "{%0,%1,%2,%3}, {%4,%5,%6,%7}, {%8,%9}, {%0,%1,%2,%3};"
                 : "+f"(c[0]), "+f"(c[1]), "+f"(c[2]), "+f"(c[3])
                 : "r"(a[0]), "r"(a[1]), "r"(a[2]), "r"(a[3]), "r"(b[0]), "r"(b[1]));
}

__device__ __forceinline__ uint32_t pack_bf16(float lo, float hi) {
    uint32_t r;
    asm("cvt.rn.bf16x2.f32 %0, %1, %2;" : "=r"(r) : "f"(hi), "f"(lo));
    return r;
}
__device__ __forceinline__ void split_pair(float a, float b, uint32_t& h, uint32_t& l) {
    h = pack_bf16(a, b);
    __nv_bfloat162 hb = *reinterpret_cast<__nv_bfloat162*>(&h);
    l = pack_bf16(a - __bfloat162float(hb.x), b - __bfloat162float(hb.y));
}

// ================= light GEMM: CTA 128x128, BK=64, 3-stage =================
#define GBK 64
#define GROW 144                         // smem row stride bytes (64 bf16 + 8 pad)
#define TILE_B (128 * GROW)              // 18432
#define STAGE_B (4 * TILE_B)             // 73728 (Ah, Al, Bh, Bl)
#define GEMM_SMEM (3 * STAGE_B)          // 221184

__device__ __forceinline__ void load_stage(uint32_t stage,
                                           const __nv_bfloat16* __restrict__ Ah,
                                           const __nv_bfloat16* __restrict__ Al,
                                           const __nv_bfloat16* __restrict__ Bh,
                                           const __nv_bfloat16* __restrict__ Bl,
                                           int K, int k0, int tid)
{
    const __nv_bfloat16* tp[4] = {Ah, Al, Bh, Bl};
#pragma unroll
    for (int t = 0; t < 4; t++) {
        const char* src_base = (const char*)tp[t] + (size_t)k0 * 2;
        uint32_t dtile = stage + t * TILE_B;
#pragma unroll
        for (int it = 0; it < 4; it++) {
            int u = tid + it * 256;
            int row = u >> 3;
            int ch = (u & 7) * 16;
            CP_ASYNC16(dtile + row * GROW + ch, src_base + (size_t)row * K * 2 + ch);
        }
    }
    CP_COMMIT();
}

__device__ __forceinline__ void hmma_gemm_body(const __nv_bfloat16* __restrict__ Ah,
                                               const __nv_bfloat16* __restrict__ Al,
                                               const __nv_bfloat16* __restrict__ Bh,
                                               const __nv_bfloat16* __restrict__ Bl,
                                               float* __restrict__ C, int K, int ldc,
                                               int gm0, int gn0)
{
    extern __shared__ char smem[];
    const uint32_t sb = smem_u32(smem);
    const int tid = threadIdx.x;
    const int wid = tid >> 5;
    const int lane = tid & 31;
    const int warpM = (wid >> 2) * 64;
    const int warpN = (wid & 3) * 32;
    const int NC = K / GBK;

    const __nv_bfloat16* Ah0 = Ah + (size_t)gm0 * K;
    const __nv_bfloat16* Al0 = Al + (size_t)gm0 * K;
    const __nv_bfloat16* Bh0 = Bh + (size_t)gn0 * K;
    const __nv_bfloat16* Bl0 = Bl + (size_t)gn0 * K;

    float acc[4][4][4];
#pragma unroll
    for (int i = 0; i < 4; i++)
#pragma unroll
        for (int j = 0; j < 4; j++)
#pragma unroll
            for (int v = 0; v < 4; v++) acc[i][j][v] = 0.f;

    const uint32_t a_off = (uint32_t)((warpM + (lane & 15)) * GROW + ((lane >> 4) << 4));
    const uint32_t b_rowsel = (uint32_t)((warpN + ((lane >> 4) & 1) * 8 + (lane & 7)) * GROW +
                                         (((lane >> 3) & 1) << 4));

    load_stage(sb + 0 * STAGE_B, Ah0, Al0, Bh0, Bl0, K, 0, tid);
    load_stage(sb + 1 * STAGE_B, Ah0, Al0, Bh0, Bl0, K, GBK, tid);

    for (int c = 0; c < NC; c++) {
        if (c + 1 < NC) { CP_WAIT1(); } else { CP_WAIT0(); }
        __syncthreads();

        if (c + 2 < NC)
            load_stage(sb + ((c + 2) % 3) * STAGE_B, Ah0, Al0, Bh0, Bl0, K, (c + 2) * GBK, tid);

        const uint32_t base = sb + (c % 3) * STAGE_B;
#pragma unroll
        for (int kk = 0; kk < 64; kk += 16) {
            uint32_t aH[4][4], aL[4][4], bH4[2][4], bL4[2][4];
#pragma unroll
            for (int mi = 0; mi < 4; mi++) {
                uint32_t ao = a_off + (uint32_t)(mi * 16 * GROW) + kk * 2;
                ldsm_x4(aH[mi], base + 0 * TILE_B + ao);
                ldsm_x4(aL[mi], base + 1 * TILE_B + ao);
            }
#pragma unroll
            for (int p = 0; p < 2; p++) {
                uint32_t bo = b_rowsel + (uint32_t)(p * 16 * GROW) + kk * 2;
                ldsm_x4(bH4[p], base + 2 * TILE_B + bo);
                ldsm_x4(bL4[p], base + 3 * TILE_B + bo);
            }
#pragma unroll
            for (int mi = 0; mi < 4; mi++)
#pragma unroll
                for (int p = 0; p < 2; p++) {
                    mma16816(acc[mi][2 * p],     aH[mi], bH4[p]);
                    mma16816(acc[mi][2 * p],     aL[mi], bH4[p]);
                    mma16816(acc[mi][2 * p],     aH[mi], bL4[p]);
                    mma16816(acc[mi][2 * p + 1], aH[mi], bH4[p] + 2);
                    mma16816(acc[mi][2 * p + 1], aL[mi], bH4[p] + 2);
                    mma16816(acc[mi][2 * p + 1], aH[mi], bL4[p] + 2);
                }
        }
    }

    const int r0 = lane >> 2;
    const int c0 = (lane & 3) * 2;
#pragma unroll
    for (int mi = 0; mi < 4; mi++)
#pragma unroll
        for (int nj = 0; nj < 4; nj++) {
            float* cp = C + (size_t)(gm0 + warpM + mi * 16 + r0) * ldc + gn0 + warpN + nj * 8 + c0;
            *reinterpret_cast<float2*>(cp) = make_float2(acc[mi][nj][0], acc[mi][nj][1]);
            *reinterpret_cast<float2*>(cp + 8 * ldc) = make_float2(acc[mi][nj][2], acc[mi][nj][3]);
        }
}

// ================= wide GEMM: CTA 128x256, BK=64, 2-stage, warp tile 64x64 =================
#define WA_TILE (128 * GROW)             // 18432 per (h|l)
#define WB_TILE (256 * GROW)             // 36864 per (h|l)
#define WSTG (2 * WA_TILE + 2 * WB_TILE) // 110592

__device__ __forceinline__ void load_stage_wide(uint32_t stage,
                                                const __nv_bfloat16* __restrict__ Ah,
                                                const __nv_bfloat16* __restrict__ Al,
                                                const __nv_bfloat16* __restrict__ Bh,
                                                const __nv_bfloat16* __restrict__ Bl,
                                                int K, int k0, int tid)
{
    {
        const __nv_bfloat16* tp[2] = {Ah, Al};
#pragma unroll
        for (int t = 0; t < 2; t++) {
            const char* src = (const char*)tp[t] + (size_t)k0 * 2;
            uint32_t dtile = stage + t * WA_TILE;
#pragma unroll
            for (int it = 0; it < 4; it++) {
                int u = tid + it * 256;       // 0..1023 -> 128 rows
                int row = u >> 3;
                int ch = (u & 7) * 16;
                CP_ASYNC16(dtile + row * GROW + ch, src + (size_t)row * K * 2 + ch);
            }
        }
    }
    {
        const __nv_bfloat16* tp[2] = {Bh, Bl};
#pragma unroll
        for (int t = 0; t < 2; t++) {
            const char* src = (const char*)tp[t] + (size_t)k0 * 2;
            uint32_t dtile = stage + 2 * WA_TILE + t * WB_TILE;
#pragma unroll
            for (int it = 0; it < 8; it++) {
                int u = tid + it * 256;       // 0..2047 -> 256 rows
                int row = u >> 3;
                int ch = (u & 7) * 16;
                CP_ASYNC16(dtile + row * GROW + ch, src + (size_t)row * K * 2 + ch);
            }
        }
    }
    CP_COMMIT();
}

__device__ __forceinline__ void hmma_gemm_wide(const __nv_bfloat16* __restrict__ Ah,
                                               const __nv_bfloat16* __restrict__ Al,
                                               const __nv_bfloat16* __restrict__ Bh,
                                               const __nv_bfloat16* __restrict__ Bl,
                                               float* __restrict__ C, int K, int ldc,
                                               int gm0, int gn0)
{
    extern __shared__ char smem[];
    const uint32_t sb = smem_u32(smem);
    const int tid = threadIdx.x;
    const int wid = tid >> 5;
    const int lane = tid & 31;
    const int warpM = (wid >> 2) * 64;       // 2 M-groups
    const int warpN = (wid & 3) * 64;        // 4 N-groups of 64
    const int NC = K / GBK;

    const __nv_bfloat16* Ah0 = Ah + (size_t)gm0 * K;
    const __nv_bfloat16* Al0 = Al + (size_t)gm0 * K;
    const __nv_bfloat16* Bh0 = Bh + (size_t)gn0 * K;
    const __nv_bfloat16* Bl0 = Bl + (size_t)gn0 * K;

    float acc[4][8][4];
#pragma unroll
    for (int i = 0; i < 4; i++)
#pragma unroll
        for (int j = 0; j < 8; j++)
#pragma unroll
            for (int v = 0; v < 4; v++) acc[i][j][v] = 0.f;

    const uint32_t a_off = (uint32_t)((warpM + (lane & 15)) * GROW + ((lane >> 4) << 4));
    const uint32_t b_rowsel = (uint32_t)((warpN + ((lane >> 4) & 1) * 8 + (lane & 7)) * GROW +
                                         (((lane >> 3) & 1) << 4));

    load_stage_wide(sb + 0 * WSTG, Ah0, Al0, Bh0, Bl0, K, 0, tid);
    load_stage_wide(sb + 1 * WSTG, Ah0, Al0, Bh0, Bl0, K, GBK, tid);

    for (int c = 0; c < NC; c++) {
        if (c + 1 < NC) { CP_WAIT1(); } else { CP_WAIT0(); }
        __syncthreads();

        const uint32_t base = sb + (c & 1) * WSTG;
#pragma unroll 1
        for (int kk = 0; kk < 4; kk++) {
            uint32_t aH[4][4], aL[4][4];
#pragma unroll
            for (int mi = 0; mi < 4; mi++) {
                uint32_t ao = a_off + (uint32_t)(mi * 16 * GROW) + kk * 32;
                ldsm_x4(aH[mi], base + ao);
                ldsm_x4(aL[mi], base + WA_TILE + ao);
            }
#pragma unroll
            for (int p = 0; p < 4; p++) {
                uint32_t bo = b_rowsel + (uint32_t)(p * 16 * GROW) + kk * 32;
                uint32_t bH4[4], bL4[4];
                ldsm_x4(bH4, base + 2 * WA_TILE + bo);
                ldsm_x4(bL4, base + 2 * WA_TILE + WB_TILE + bo);
#pragma unroll
                for (int mi = 0; mi < 4; mi++) {
                    mma16816(acc[mi][2 * p],     aH[mi], bH4);
                    mma16816(acc[mi][2 * p],     aL[mi], bH4);
                    mma16816(acc[mi][2 * p],     aH[mi], bL4);
                    mma16816(acc[mi][2 * p + 1], aH[mi], bH4 + 2);
                    mma16816(acc[mi][2 * p + 1], aL[mi], bH4 + 2);
                    mma16816(acc[mi][2 * p + 1], aH[mi], bL4 + 2);
                }
            }
        }
        __syncthreads();
        if (c + 2 < NC)
            load_stage_wide(base, Ah0, Al0, Bh0, Bl0, K, (c + 2) * GBK, tid);
    }

    const int r0 = lane >> 2;
    const int c0 = (lane & 3) * 2;
#pragma unroll
    for (int mi = 0; mi < 4; mi++)
#pragma unroll
        for (int nj = 0; nj < 8; nj++) {
            float* cp = C + (size_t)(gm0 + warpM + mi * 16 + r0) * ldc + gn0 + warpN + nj * 8 + c0;
            *reinterpret_cast<float2*>(cp) = make_float2(acc[mi][nj][0], acc[mi][nj][1]);
            *reinterpret_cast<float2*>(cp + 8 * ldc) = make_float2(acc[mi][nj][2], acc[mi][nj][3]);
        }
}

// Fused Q/K/V projections: 128 wide q CTAs (heavy, scheduled first) + 64 k + 64 v light.
__global__ __launch_bounds__(256, 1) void gemm_qkv_kernel() {
    const int bid = blockIdx.x;
    if (bid < 128) {
        hmma_gemm_wide(g_xh, g_xl, g_wqh, g_wql, g_qraw, DIN, DOUT,
                       (bid >> 3) * 128, (bid & 7) * 256);
    } else if (bid < 192) {
        const int b = bid - 128;
        hmma_gemm_body(g_xh, g_xl, g_wkh, g_wkl, g_kraw, DIN, KVD,
                       (b >> 2) * 128, (b & 3) * 128);
    } else {
        const int b = bid - 192;
        hmma_gemm_body(g_xh, g_xl, g_wvh, g_wvl, g_vraw, DIN, KVD,
                       (b >> 2) * 128, (b & 3) * 128);
    }
}

__global__ __launch_bounds__(256, 1) void gemm_o_kernel(float* __restrict__ out) {
    hmma_gemm_wide(g_ch, g_cl, g_woh, g_wol, out, DOUT, DIN,
                   blockIdx.y * 128, blockIdx.x * 256);
}

// ---------------- converts ----------------
__device__ __forceinline__ void wconv_body(const float* __restrict__ W,
                                           __nv_bfloat16* __restrict__ Bh,
                                           __nv_bfloat16* __restrict__ Bl,
                                           int R, int Cc, int bx, int by)
{
    __shared__ float t[32][33];
    const int c0 = bx * 32;
    const int r0 = by * 32;
    const int tx = threadIdx.x;
    const int ty = threadIdx.y;
#pragma unroll
    for (int i = ty; i < 32; i += 8)
        t[i][tx] = W[(size_t)(r0 + i) * Cc + c0 + tx];
    __syncthreads();
#pragma unroll
    for (int i = ty; i < 32; i += 8) {
        float v = t[tx][i];
        size_t o = (size_t)(c0 + i) * R + r0 + tx;
        __nv_bfloat16 h = __float2bfloat16(v);
        Bh[o] = h;
        Bl[o] = __float2bfloat16(v - __bfloat162float(h));
    }
}

// fused converts: x split (8192) + wq (4096) + wk (1024) + wv (1024) + wo (4096) = 18432 CTAs
__global__ void conv_all_kernel(const float* __restrict__ x,
                                const float* __restrict__ Wq, const float* __restrict__ Wk,
                                const float* __restrict__ Wv, const float* __restrict__ Wo)
{
    int b = blockIdx.x;
    if (b < 8192) {
        int tid = threadIdx.y * 32 + threadIdx.x;
        int i = (b * 256 + tid) * 2;
        float2 v = *reinterpret_cast<const float2*>(x + i);
        uint32_t h, l;
        split_pair(v.x, v.y, h, l);
        reinterpret_cast<uint32_t*>(g_xh)[i >> 1] = h;
        reinterpret_cast<uint32_t*>(g_xl)[i >> 1] = l;
        return;
    }
    b -= 8192;
    if (b < 4096) {
        wconv_body(Wq, g_wqh, g_wql, DIN, DOUT, b & 63, b >> 6);
    } else if (b < 5120) {
        b -= 4096;
        wconv_body(Wk, g_wkh, g_wkl, DIN, KVD, b & 15, b >> 4);
    } else if (b < 6144) {
        b -= 5120;
        wconv_body(Wv, g_wvh, g_wvl, DIN, KVD, b & 15, b >> 4);
    } else {
        b -= 6144;
        wconv_body(Wo, g_woh, g_wol, DOUT, DIN, b & 63, b >> 6);
    }
}

// V: fp32 [s][kv*64+d] -> split bf16 transposed [kv][d][s]
__global__ void vsplit_kernel() {
    __shared__ float t[32][33];
    const int s0 = blockIdx.x * 32;
    const int d0 = blockIdx.y * 32;
    const int kv = blockIdx.z;
    const int tx = threadIdx.x;
    const int ty = threadIdx.y;
#pragma unroll
    for (int i = ty; i < 32; i += 8)
        t[i][tx] = g_vraw[(size_t)(s0 + i) * KVD + kv * 64 + d0 + tx];
    __syncthreads();
#pragma unroll
    for (int i = ty; i < 32; i += 8) {
        float v = t[tx][i];
        size_t o = ((size_t)kv * 64 + d0 + i) * SLEN + s0 + tx;
        __nv_bfloat16 h = __float2bfloat16(v);
        g_vth[o] = h;
        g_vtl[o] = __float2bfloat16(v - __bfloat162float(h));
    }
}

// ---------------- RMSNorm + RoPE -> split bf16 (vectorized float2) ----------------
// block (32, 8): warp ty handles unit u = by*8+ty; thread handles d = 2*tx, 2*tx+1.
__global__ void normrope_kernel(const float* __restrict__ cosb,
                                const float* __restrict__ sinb,
                                const float* __restrict__ qw,
                                const float* __restrict__ kw)
{
    const int s = blockIdx.x;
    const int ty = threadIdx.y;
    const int tx = threadIdx.x;
    const int u = blockIdx.y * 8 + ty;   // 0..39
    const int d2 = tx * 2;
    __shared__ float sh[8][64];

    float2 val;
    float2 w;
    if (u < 32) {
        val = *reinterpret_cast<const float2*>(&g_qraw[(size_t)s * DOUT + u * 64 + d2]);
        w = *reinterpret_cast<const float2*>(&qw[d2]);
    } else {
        val = *reinterpret_cast<const float2*>(&g_kraw[(size_t)s * KVD + (u - 32) * 64 + d2]);
        w = *reinterpret_cast<const float2*>(&kw[d2]);
    }
    float sq = val.x * val.x + val.y * val.y;
#pragma unroll
    for (int mk = 16; mk; mk >>= 1) sq += __shfl_xor_sync(0xffffffffu, sq, mk);
    const float rn = rsqrtf(sq * (1.0f / 64.0f) + 1e-6f);
    float2 xn = make_float2(val.x * rn * w.x, val.y * rn * w.y);
    sh[ty][d2] = xn.x;
    sh[ty][d2 + 1] = xn.y;
    __syncwarp();
    float2 rot;
    if (tx < 16) { rot = make_float2(-sh[ty][d2 + 32], -sh[ty][d2 + 33]); }
    else         { rot = make_float2( sh[ty][d2 - 32],  sh[ty][d2 - 31]); }
    float2 cs = *reinterpret_cast<const float2*>(&cosb[s * 64 + d2]);
    float2 sn = *reinterpret_cast<const float2*>(&sinb[s * 64 + d2]);
    float o0 = xn.x * cs.x + rot.x * sn.x;
    float o1 = xn.y * cs.y + rot.y * sn.y;
    uint32_t hh, ll;
    split_pair(o0, o1, hh, ll);
    if (u < 32) {
        size_t idx = ((size_t)u * SLEN + s) * 64 + d2;
        *reinterpret_cast<uint32_t*>(&g_qh[idx]) = hh;
        *reinterpret_cast<uint32_t*>(&g_ql[idx]) = ll;
    } else {
        size_t idx = ((size_t)(u - 32) * SLEN + s) * 64 + d2;
        *reinterpret_cast<uint32_t*>(&g_kbh[idx]) = hh;
        *reinterpret_cast<uint32_t*>(&g_kbl[idx]) = ll;
    }
}

// ---------------- Flash attention (HMMA split-bf16, causal, GQA) ----------------
// grid (32 heads, 16 q-blocks), 256 threads (8 warps x 16 rows). Q tile 128, KV tile 64.
#define ATS 144
#define QTILE (128 * ATS)
#define KTILE (64 * ATS)
#define ATT_SMEM (2 * QTILE + 8 * KTILE)   // 110592

__global__ __launch_bounds__(256) void attn_kernel()
{
    extern __shared__ char smem[];
    const uint32_t sb = smem_u32(smem);
    const int tid = threadIdx.x;
    const int lane = tid & 31;
    const int wid = tid >> 5;
    const int h = blockIdx.x;
    const int qb = 15 - (int)blockIdx.y;
    const int s0 = qb * 128;
    const int kvh = h >> 2;

    const uint32_t SQH = sb, SQL = sb + QTILE, SKV = sb + 2 * QTILE;

    const char* qh = (const char*)g_qh + (((size_t)h * SLEN + s0) * 64) * 2;
    const char* ql = (const char*)g_ql + (((size_t)h * SLEN + s0) * 64) * 2;
    const char* kh = (const char*)g_kbh + ((size_t)kvh * SLEN * 64) * 2;
    const char* kl = (const char*)g_kbl + ((size_t)kvh * SLEN * 64) * 2;
    const char* vh = (const char*)g_vth + ((size_t)kvh * 64 * SLEN) * 2;
    const char* vl = (const char*)g_vtl + ((size_t)kvh * 64 * SLEN) * 2;

#pragma unroll
    for (int i = 0; i < 4; i++) {
        int u = tid + i * 256;
        int row = u >> 3;
        int ch = (u & 7) * 16;
        CP_ASYNC16(SQH + row * ATS + ch, qh + (size_t)row * 128 + ch);
        CP_ASYNC16(SQL + row * ATS + ch, ql + (size_t)row * 128 + ch);
    }
    {
        uint32_t base = SKV;
#pragma unroll
        for (int i = 0; i < 2; i++) {
            int u = tid + i * 256;
            int row = u >> 3;
            int ch = (u & 7) * 16;
            CP_ASYNC16(base + 0 * KTILE + row * ATS + ch, kh + (size_t)row * 128 + ch);
            CP_ASYNC16(base + 1 * KTILE + row * ATS + ch, kl + (size_t)row * 128 + ch);
            CP_ASYNC16(base + 2 * KTILE + row * ATS + ch, vh + (size_t)row * SLEN * 2 + ch);
            CP_ASYNC16(base + 3 * KTILE + row * ATS + ch, vl + (size_t)row * SLEN * 2 + ch);
        }
    }
    CP_COMMIT();

    const int warpM = wid * 16;
    const uint32_t a_off = (uint32_t)((warpM + (lane & 15)) * ATS + ((lane >> 4) << 4));
    const uint32_t b_rowsel = (uint32_t)((((lane >> 4) & 1) * 8 + (lane & 7)) * ATS +
                                         (((lane >> 3) & 1) << 4));

    float m0 = -1e30f, m1 = -1e30f, l0 = 0.f, l1 = 0.f;
    float o[8][4];
#pragma unroll
    for (int j = 0; j < 8; j++)
#pragma unroll
        for (int v = 0; v < 4; v++) o[j][v] = 0.f;

    const float scale = 0.125f;
    const int kbmax = 2 * qb + 1;

    for (int kb = 0; kb <= kbmax; kb++) {
        const int st = kb & 1;
        const int t0 = kb * 64;
        if (kb < kbmax) {
            uint32_t base = SKV + (st ^ 1) * 4 * KTILE;
            const size_t t1 = (size_t)(kb + 1) * 64;
#pragma unroll
            for (int i = 0; i < 2; i++) {
                int u = tid + i * 256;
                int row = u >> 3;
                int ch = (u & 7) * 16;
                CP_ASYNC16(base + 0 * KTILE + row * ATS + ch, kh + (t1 + row) * 128 + ch);
                CP_ASYNC16(base + 1 * KTILE + row * ATS + ch, kl + (t1 + row) * 128 + ch);
                CP_ASYNC16(base + 2 * KTILE + row * ATS + ch, vh + (size_t)row * SLEN * 2 + t1 * 2 + ch);
                CP_ASYNC16(base + 3 * KTILE + row * ATS + ch, vl + (size_t)row * SLEN * 2 + t1 * 2 + ch);
            }
            CP_COMMIT();
            CP_WAIT1();
        } else {
            CP_WAIT0();
        }
        __syncthreads();

        const uint32_t KH = SKV + st * 4 * KTILE;
        const uint32_t KL = KH + KTILE, VH = KL + KTILE, VL = VH + KTILE;

        float s_acc[8][4];
#pragma unroll
        for (int j = 0; j < 8; j++)
#pragma unroll
            for (int v = 0; v < 4; v++) s_acc[j][v] = 0.f;

#pragma unroll
        for (int kk = 0; kk < 4; kk++) {
            uint32_t aH[4], aL[4];
            ldsm_x4(aH, SQH + a_off + kk * 32);
            ldsm_x4(aL, SQL + a_off + kk * 32);
#pragma unroll
            for (int p = 0; p < 4; p++) {
                uint32_t bo = (uint32_t)(p * 16 * ATS) + b_rowsel + kk * 32;
                uint32_t bH4[4], bL4[4];
                ldsm_x4(bH4, KH + bo);
                ldsm_x4(bL4, KL + bo);
                mma16816(s_acc[2 * p],     aH, bH4);
                mma16816(s_acc[2 * p],     aL, bH4);
                mma16816(s_acc[2 * p],     aH, bL4);
                mma16816(s_acc[2 * p + 1], aH, bH4 + 2);
                mma16816(s_acc[2 * p + 1], aL, bH4 + 2);
                mma16816(s_acc[2 * p + 1], aH, bL4 + 2);
            }
        }

#pragma unroll
        for (int j = 0; j < 8; j++)
#pragma unroll
            for (int v = 0; v < 4; v++) s_acc[j][v] *= scale;

        if (t0 + 63 > s0 + warpM) {
            const int rg0 = s0 + warpM + (lane >> 2);
#pragma unroll
            for (int nj = 0; nj < 8; nj++) {
                const int cg = t0 + nj * 8 + (lane & 3) * 2;
#pragma unroll
                for (int e = 0; e < 2; e++) {
                    if (cg + e > rg0) s_acc[nj][e] = -1e30f;
                    if (cg + e > rg0 + 8) s_acc[nj][2 + e] = -1e30f;
                }
            }
        }

        float mx0 = -1e30f, mx1 = -1e30f;
#pragma unroll
        for (int nj = 0; nj < 8; nj++) {
            mx0 = fmaxf(mx0, fmaxf(s_acc[nj][0], s_acc[nj][1]));
            mx1 = fmaxf(mx1, fmaxf(s_acc[nj][2], s_acc[nj][3]));
        }
        mx0 = fmaxf(mx0, __shfl_xor_sync(0xffffffffu, mx0, 1));
        mx0 = fmaxf(mx0, __shfl_xor_sync(0xffffffffu, mx0, 2));
        mx1 = fmaxf(mx1, __shfl_xor_sync(0xffffffffu, mx1, 1));
        mx1 = fmaxf(mx1, __shfl_xor_sync(0xffffffffu, mx1, 2));
        const float M0 = fmaxf(m0, mx0), M1 = fmaxf(m1, mx1);
        const float corr0 = __expf(m0 - M0), corr1 = __expf(m1 - M1);
        m0 = M0; m1 = M1;

        float rs0 = 0.f, rs1 = 0.f;
#pragma unroll
        for (int nj = 0; nj < 8; nj++) {
            s_acc[nj][0] = __expf(s_acc[nj][0] - M0);
            s_acc[nj][1] = __expf(s_acc[nj][1] - M0);
            s_acc[nj][2] = __expf(s_acc[nj][2] - M1);
            s_acc[nj][3] = __expf(s_acc[nj][3] - M1);
            rs0 += s_acc[nj][0] + s_acc[nj][1];
            rs1 += s_acc[nj][2] + s_acc[nj][3];
        }
        rs0 += __shfl_xor_sync(0xffffffffu, rs0, 1);
        rs0 += __shfl_xor_sync(0xffffffffu, rs0, 2);
        rs1 += __shfl_xor_sync(0xffffffffu, rs1, 1);
        rs1 += __shfl_xor_sync(0xffffffffu, rs1, 2);
        l0 = l0 * corr0 + rs0;
        l1 = l1 * corr1 + rs1;

#pragma unroll
        for (int j = 0; j < 8; j++) {
            o[j][0] *= corr0; o[j][1] *= corr0;
            o[j][2] *= corr1; o[j][3] *= corr1;
        }

#pragma unroll
        for (int kt = 0; kt < 4; kt++) {
            uint32_t pH[4], pL[4];
            split_pair(s_acc[2 * kt][0],     s_acc[2 * kt][1],     pH[0], pL[0]);
            split_pair(s_acc[2 * kt][2],     s_acc[2 * kt][3],     pH[1], pL[1]);
            split_pair(s_acc[2 * kt + 1][0], s_acc[2 * kt + 1][1], pH[2], pL[2]);
            split_pair(s_acc[2 * kt + 1][2], s_acc[2 * kt + 1][3], pH[3], pL[3]);
#pragma unroll
            for (int p = 0; p < 4; p++) {
                uint32_t vo = (uint32_t)(p * 16 * ATS) + b_rowsel + kt * 32;
                uint32_t vH4[4], vL4[4];
                ldsm_x4(vH4, VH + vo);
                ldsm_x4(vL4, VL + vo);
                mma16816(o[2 * p],     pH, vH4);
                mma16816(o[2 * p],     pL, vH4);
                mma16816(o[2 * p],     pH, vL4);
                mma16816(o[2 * p + 1], pH, vH4 + 2);
                mma16816(o[2 * p + 1], pL, vH4 + 2);
                mma16816(o[2 * p + 1], pH, vL4 + 2);
            }
        }
        __syncthreads();
    }

    const float inv0 = 1.0f / l0, inv1 = 1.0f / l1;
    const int r0 = s0 + warpM + (lane >> 2);
    const int r1 = r0 + 8;
    const int cb = h * 64 + (lane & 3) * 2;
#pragma unroll
    for (int dj = 0; dj < 8; dj++) {
        const int col = cb + dj * 8;
        uint32_t hh, ll;
        split_pair(o[dj][0] * inv0, o[dj][1] * inv0, hh, ll);
        *reinterpret_cast<uint32_t*>(&g_ch[(size_t)r0 * DOUT + col]) = hh;
        *reinterpret_cast<uint32_t*>(&g_cl[(size_t)r0 * DOUT + col]) = ll;
        split_pair(o[dj][2] * inv1, o[dj][3] * inv1, hh, ll);
        *reinterpret_cast<uint32_t*>(&g_ch[(size_t)r1 * DOUT + col]) = hh;
        *reinterpret_cast<uint32_t*>(&g_cl[(size_t)r1 * DOUT + col]) = ll;
    }
}

// ---------------- launch ----------------
extern "C" void kernel_launch(void* const* d_in, const int* in_sizes, int n_in,
                              void* d_out, int out_size)
{
    const float* x    = (const float*)d_in[0];
    const float* cosb = (const float*)d_in[2];
    const float* sinb = (const float*)d_in[3];
    const float* Wq   = (const float*)d_in[4];
    const float* Wk   = (const float*)d_in[5];
    const float* Wv   = (const float*)d_in[6];
    const float* Wo   = (const float*)d_in[7];
    const float* qw   = (const float*)d_in[8];
    const float* kw   = (const float*)d_in[9];
    float* out = (float*)d_out;

    (void)in_sizes; (void)n_in; (void)out_size;

    cudaFuncSetAttribute(gemm_qkv_kernel, cudaFuncAttributeMaxDynamicSharedMemorySize, GEMM_SMEM);
    cudaFuncSetAttribute(gemm_o_kernel,   cudaFuncAttributeMaxDynamicSharedMemorySize, GEMM_SMEM);
    cudaFuncSetAttribute(attn_kernel,     cudaFuncAttributeMaxDynamicSharedMemorySize, ATT_SMEM);

    conv_all_kernel<<<18432, dim3(32, 8)>>>(x, Wq, Wk, Wv, Wo);

    gemm_qkv_kernel<<<256, 256, GEMM_SMEM>>>();

    normrope_kernel<<<dim3(SLEN, 5), dim3(32, 8)>>>(cosb, sinb, qw, kw);
    vsplit_kernel<<<dim3(SLEN / 32, 2, NKV), dim3(32, 8)>>>();

    attn_kernel<<<dim3(NH, 16), 256, ATT_SMEM>>>();

    gemm_o_kernel<<<dim3(DOUT / 256, SLEN / 128), 256, GEMM_SMEM>>>(out);
}